// round 7
// baseline (speedup 1.0000x reference)
#include <cuda_runtime.h>
#include <cuda_bf16.h>
#include <cuda_fp16.h>
#include <math_constants.h>
#include <cstdint>
#include <cstddef>

#define DEMB 768
#define KSEL 32
#define K2   128               // blockmin threshold rank
#define TILE_N 128
#define KC   32                // k elements per chunk
#define NCH  (DEMB / KC)       // 24
#define STAGES 4
#define MAXB 256
#define MAXN 200000
#define MAXT ((MAXN + TILE_N - 1) / TILE_N)   // 1563
#define CCAP 1024
#define BMPAD 2048
#define SPITCH 136             // halves per staged row (272B, conflict-free)

// stage layout: A fp8 (256 rows x 48B pitch, 32B data) then B fp32 (128 rows x 128B, swizzled)
#define A_PITCH 48
#define A_BYTES (256 * A_PITCH)            // 12288
#define B_BYTES (128 * 128)                // 16384
#define STAGE_BYTES (A_BYTES + B_BYTES)    // 28672

// ---- device scratch ----
__device__ __align__(16) uint8_t g_Q8[MAXB * DEMB];
__device__ __align__(16) __half g_S[(size_t)MAXB * (size_t)MAXN];
__device__ __align__(16) float g_blkmin[MAXB * MAXT];

__device__ __forceinline__ uint32_t smem_u32(const void* p) {
    uint32_t a;
    asm("{ .reg .u64 t; cvta.to.shared.u64 t, %1; cvt.u32.u64 %0, t; }" : "=r"(a) : "l"(p));
    return a;
}
__device__ __forceinline__ void cp16(uint32_t dst, const void* src) {
    asm volatile("cp.async.ca.shared.global [%0], [%1], 16;" :: "r"(dst), "l"(src));
}
#define CP_COMMIT() asm volatile("cp.async.commit_group;" ::: "memory")
#define CP_WAIT2()  asm volatile("cp.async.wait_group 2;" ::: "memory")

__device__ __forceinline__ uint32_t pack_e4m3(float f0, float f1, float f2, float f3) {
    uint16_t lo, hi;
    asm("cvt.rn.satfinite.e4m3x2.f32 %0, %1, %2;" : "=h"(lo) : "f"(f1), "f"(f0));
    asm("cvt.rn.satfinite.e4m3x2.f32 %0, %1, %2;" : "=h"(hi) : "f"(f3), "f"(f2));
    return (uint32_t)lo | ((uint32_t)hi << 16);
}
__device__ __forceinline__ void mma_fp8(float* c, const uint32_t* a, const uint32_t* b) {
    asm volatile(
        "mma.sync.aligned.m16n8k32.row.col.f32.e4m3.e4m3.f32 "
        "{%0,%1,%2,%3}, {%4,%5,%6,%7}, {%8,%9}, {%0,%1,%2,%3};"
        : "+f"(c[0]), "+f"(c[1]), "+f"(c[2]), "+f"(c[3])
        : "r"(a[0]), "r"(a[1]), "r"(a[2]), "r"(a[3]), "r"(b[0]), "r"(b[1]));
}
__device__ __forceinline__ unsigned enc(float f) {
    unsigned u = __float_as_uint(f);
    return (u & 0x80000000u) ? ~u : (u | 0x80000000u);
}
__device__ __forceinline__ float dec(unsigned u) {
    u = (u & 0x80000000u) ? (u & 0x7fffffffu) : ~u;
    return __uint_as_float(u);
}
__device__ __forceinline__ unsigned long long mkkey(float v, int idx) {
    return ((unsigned long long)enc(v) << 32) | (unsigned)idx;
}

// ---------------- Q fp32 -> e4m3 (zero-pad to MAXB rows) ----------------
__global__ void convq_kernel(const float* __restrict__ Q, int total) {
    int i = blockIdx.x * blockDim.x + threadIdx.x;
    if (i < MAXB * DEMB / 4) {
        int e = i * 4;
        float4 v = make_float4(0.f, 0.f, 0.f, 0.f);
        if (e < total) v = *(const float4*)&Q[e];
        ((uint32_t*)g_Q8)[i] = pack_e4m3(v.x, v.y, v.z, v.w);
    }
}

// ---------------- FP8 MMA GEMM, M=256 x N-tile=128, cp.async 4-stage ----------------
__global__ __launch_bounds__(512, 1)
void gemm_fp8_kernel(const float* __restrict__ X, int B, int N, int ntiles)
{
    extern __shared__ __align__(16) char dsm[];
    __shared__ float    x2p[TILE_N];
    __shared__ unsigned bmu[256];

    const int tid  = threadIdx.x;
    const int lane = tid & 31;
    const int warp = tid >> 5;
    const int wm = warp >> 2, wn = warp & 3;
    const int fr = lane >> 2, fc = lane & 3;
    const int n0 = blockIdx.x * TILE_N;

    const uint32_t sb = smem_u32(dsm);

    // A cp.async: one 16B chunk per thread (256 rows x 2 chunks)
    const int rA = tid >> 1, hA = tid & 1;
    const char* asrc = (const char*)g_Q8 + (size_t)rA * DEMB + hA * 16;
    const uint32_t adst = sb + rA * A_PITCH + hA * 16;

    // B cp.async: two 16B chunks per thread (128 rows x 8 chunks, XOR-swizzled)
    const int rB0 = tid >> 3,         cB0 = tid & 7;
    const int rB1 = (tid + 512) >> 3, cB1 = tid & 7;   // rB1 = rB0 + 64
    const float* bsrc0 = &X[(size_t)min(n0 + rB0, N - 1) * DEMB + cB0 * 4];
    const float* bsrc1 = &X[(size_t)min(n0 + rB1, N - 1) * DEMB + cB1 * 4];
    const uint32_t bdst0 = sb + A_BYTES + rB0 * 128 + ((cB0 ^ ((rB0 & 1) << 2)) * 16);
    const uint32_t bdst1 = sb + A_BYTES + rB1 * 128 + ((cB1 ^ ((rB1 & 1) << 2)) * 16);

    if (tid < 256) bmu[tid] = 0xFFFFFFFFu;

    // prologue: stages 0..2
    #pragma unroll
    for (int s = 0; s < 3; s++) {
        cp16(adst + s * STAGE_BYTES, asrc + s * KC);
        cp16(bdst0 + s * STAGE_BYTES, bsrc0 + s * KC);
        cp16(bdst1 + s * STAGE_BYTES, bsrc1 + s * KC);
        CP_COMMIT();
    }

    float acc[4][4][4];
    #pragma unroll
    for (int mi = 0; mi < 4; mi++)
        #pragma unroll
        for (int ni = 0; ni < 4; ni++)
            #pragma unroll
            for (int r = 0; r < 4; r++) acc[mi][ni][r] = 0.f;

    float x2a = 0.f, x2b = 0.f;   // partial x2 for rows (tid>>3) and (tid>>3)+64

    for (int ch = 0; ch < NCH; ch++) {
        const int st = ch & 3;
        CP_WAIT2();
        __syncthreads();

        if (ch + 3 < NCH) {
            const int so = ((ch + 3) & 3) * STAGE_BYTES;
            const int ko = (ch + 3) * KC;
            cp16(adst + so, asrc + ko);
            cp16(bdst0 + so, bsrc0 + ko);
            cp16(bdst1 + so, bsrc1 + ko);
        }
        CP_COMMIT();

        const char* Ab = dsm + st * STAGE_BYTES;
        const char* Bb = Ab + A_BYTES;

        // x2 accumulation: physically-linear reads (conflict-free)
        {
            float4 v0 = *(const float4*)(Bb + tid * 16);
            float4 v1 = *(const float4*)(Bb + (tid + 512) * 16);
            x2a += fmaf(v0.x, v0.x, fmaf(v0.y, v0.y, fmaf(v0.z, v0.z, v0.w * v0.w)));
            x2b += fmaf(v1.x, v1.x, fmaf(v1.y, v1.y, fmaf(v1.z, v1.z, v1.w * v1.w)));
        }

        // B fragments: fp32 (swizzled LDS.128) -> e4m3
        uint32_t bf[4][2];
        const int psw = (fr & 1) << 2;
        #pragma unroll
        for (int ni = 0; ni < 4; ni++) {
            const int n = wn * 32 + ni * 8 + fr;
            float4 f0 = *(const float4*)(Bb + n * 128 + ((fc ^ psw) * 16));
            float4 f1 = *(const float4*)(Bb + n * 128 + (((4 + fc) ^ psw) * 16));
            bf[ni][0] = pack_e4m3(f0.x, f0.y, f0.z, f0.w);
            bf[ni][1] = pack_e4m3(f1.x, f1.y, f1.z, f1.w);
        }

        // A fragments + MMAs
        #pragma unroll
        for (int mi = 0; mi < 4; mi++) {
            const int row = wm * 64 + mi * 16 + fr;
            uint32_t a[4];
            a[0] = *(const uint32_t*)(Ab + row * A_PITCH + fc * 4);
            a[1] = *(const uint32_t*)(Ab + (row + 8) * A_PITCH + fc * 4);
            a[2] = *(const uint32_t*)(Ab + row * A_PITCH + 16 + fc * 4);
            a[3] = *(const uint32_t*)(Ab + (row + 8) * A_PITCH + 16 + fc * 4);
            #pragma unroll
            for (int ni = 0; ni < 4; ni++)
                mma_fp8(acc[mi][ni], a, bf[ni]);
        }
        __syncthreads();
    }

    // reduce x2 partials: rows tid>>3 and (tid>>3)+64, 8 threads each
    x2a += __shfl_down_sync(0xffffffffu, x2a, 4, 8);
    x2a += __shfl_down_sync(0xffffffffu, x2a, 2, 8);
    x2a += __shfl_down_sync(0xffffffffu, x2a, 1, 8);
    x2b += __shfl_down_sync(0xffffffffu, x2b, 4, 8);
    x2b += __shfl_down_sync(0xffffffffu, x2b, 2, 8);
    x2b += __shfl_down_sync(0xffffffffu, x2b, 1, 8);
    if ((tid & 7) == 0) {
        x2p[tid >> 3] = x2a;
        x2p[(tid >> 3) + 64] = x2b;
    }
    __syncthreads();   // stages free from here; reuse dsm as fp16 staging tile

    // ---- epilogue v2: stage d2 (fp16) in smem + blockmin ----
    __half* stg = (__half*)dsm;   // [256][SPITCH]
    #pragma unroll
    for (int mi = 0; mi < 4; mi++) {
        const int R = wm * 64 + mi * 16 + fr;
        float mn0 = CUDART_INF_F, mn1 = CUDART_INF_F;
        #pragma unroll
        for (int ni = 0; ni < 4; ni++) {
            const int c = wn * 32 + ni * 8 + 2 * fc;
            const int n = n0 + c;
            const bool ok0 = n < N, ok1 = (n + 1) < N;
            float x2c = x2p[c], x2d = x2p[c + 1];
            float v0 = fmaf(-2.f, acc[mi][ni][0], x2c);
            float v1 = fmaf(-2.f, acc[mi][ni][1], x2d);
            float v2 = fmaf(-2.f, acc[mi][ni][2], x2c);
            float v3 = fmaf(-2.f, acc[mi][ni][3], x2d);
            *(__half2*)&stg[R * SPITCH + c]       = __floats2half2_rn(v0, v1);
            *(__half2*)&stg[(R + 8) * SPITCH + c] = __floats2half2_rn(v2, v3);
            if (ok0) { mn0 = fminf(mn0, v0); mn1 = fminf(mn1, v2); }
            if (ok1) { mn0 = fminf(mn0, v1); mn1 = fminf(mn1, v3); }
        }
        #pragma unroll
        for (int off = 1; off < 4; off <<= 1) {
            mn0 = fminf(mn0, __shfl_xor_sync(0xffffffffu, mn0, off));
            mn1 = fminf(mn1, __shfl_xor_sync(0xffffffffu, mn1, off));
        }
        if (fc == 0) {
            atomicMin(&bmu[R], enc(mn0));
            atomicMin(&bmu[R + 8], enc(mn1));
        }
    }
    __syncthreads();

    // coalesced writeout: 2 threads per row, 128B contiguous each
    {
        const int row = tid >> 1, seg = tid & 1;
        if (n0 + TILE_N <= N) {
            const uint4* src = (const uint4*)&stg[row * SPITCH + seg * 64];
            uint4* dst = (uint4*)&g_S[(size_t)row * N + n0 + seg * 64];
            #pragma unroll
            for (int i = 0; i < 8; i++) dst[i] = src[i];
        } else {
            for (int j = 0; j < 64; j++) {
                int n = n0 + seg * 64 + j;
                if (n < N) g_S[(size_t)row * N + n] = stg[row * SPITCH + seg * 64 + j];
            }
        }
    }
    if (tid < 256)
        g_blkmin[tid * ntiles + blockIdx.x] = dec(bmu[tid]);
}

// ---------------- select v2: blockmin t0 -> gather -> refine ALL -> sort exact ----------------
__global__ __launch_bounds__(256)
void select_kernel(const float* __restrict__ Q, const int* __restrict__ qsys,
                   const float* __restrict__ X, const float* __restrict__ Y,
                   const int* __restrict__ sys, const float* __restrict__ W,
                   const float* __restrict__ bias, float* __restrict__ out,
                   int B, int N, int ntiles)
{
    __shared__ float qs[DEMB];
    __shared__ float red[256];
    __shared__ unsigned long long buf[CCAP];   // 8KB: blockmin sort arena, then refined keys
    __shared__ int   cand[CCAP];
    __shared__ int   blist[CCAP];
    __shared__ int   sh_cnt, sh_nblk;

    const int b = blockIdx.x, tid = threadIdx.x;
    const int warp = tid >> 5, lane = tid & 31;

    // query row + q2
    float q2p = 0.f;
    for (int k = tid; k < DEMB; k += 256) {
        float v = Q[(size_t)b * DEMB + k];
        qs[k] = v; q2p = fmaf(v, v, q2p);
    }
    red[tid] = q2p; __syncthreads();
    for (int s = 128; s > 0; s >>= 1) { if (tid < s) red[tid] += red[tid + s]; __syncthreads(); }
    const float q2 = red[0];

    // blockmins -> sort arena (2048 floats = 8KB, fits buf exactly)
    float* bms = (float*)buf;
    const float* bmrow = &g_blkmin[b * ntiles];
    for (int i = tid; i < BMPAD; i += 256)
        bms[i] = (i < ntiles) ? bmrow[i] : CUDART_INF_F;
    if (tid == 0) { sh_cnt = 0; sh_nblk = 0; }
    __syncthreads();

    // bitonic sort -> t0 = K2-th smallest blockmin
    for (int k = 2; k <= BMPAD; k <<= 1)
        for (int j = k >> 1; j > 0; j >>= 1) {
            for (int i = tid; i < BMPAD; i += 256) {
                int ixj = i ^ j;
                if (ixj > i) {
                    float a = bms[i], c = bms[ixj];
                    if ((a > c) == ((i & k) == 0)) { bms[i] = c; bms[ixj] = a; }
                }
            }
            __syncthreads();
        }
    const float t0 = bms[K2 - 1];
    __syncthreads();

    // qualifying blocks
    for (int i = tid; i < ntiles; i += 256)
        if (bmrow[i] <= t0) {
            int p = atomicAdd(&sh_nblk, 1);
            if (p < CCAP) blist[p] = i;
        }
    __syncthreads();
    int nblk = sh_nblk; if (nblk > CCAP) nblk = CCAP;

    // gather candidate indices (fp16 values <= t0)
    const __half* srow = &g_S[(size_t)b * N];
    for (int e = tid; e < nblk * TILE_N; e += 256) {
        int blk = blist[e >> 7];
        int n = blk * TILE_N + (e & (TILE_N - 1));
        if (n < N) {
            float v = __half2float(srow[n]);
            if (v <= t0) {
                int p = atomicAdd(&sh_cnt, 1);
                if (p < CCAP) cand[p] = n;
            }
        }
    }
    __syncthreads();
    int cnt = sh_cnt; if (cnt > CCAP) cnt = CCAP;

    // pad key arena
    int P = 64; while (P < cnt) P <<= 1;
    for (int i = tid; i < P; i += 256) buf[i] = ~0ULL;
    __syncthreads();

    // exact fp32 refine of ALL candidates
    for (int c = warp; c < cnt; c += 8) {
        const int idx = cand[c];
        const float* xr = &X[(size_t)idx * DEMB];
        float dot = 0.f, xx = 0.f;
        for (int k = lane; k < DEMB; k += 32) {
            float xv = xr[k];
            dot = fmaf(qs[k], xv, dot);
            xx  = fmaf(xv, xv, xx);
        }
        #pragma unroll
        for (int off = 16; off > 0; off >>= 1) {
            dot += __shfl_xor_sync(0xffffffffu, dot, off);
            xx  += __shfl_xor_sync(0xffffffffu, xx,  off);
        }
        if (lane == 0) buf[c] = mkkey(fmaf(-2.f, dot, q2 + xx), idx);
    }
    __syncthreads();

    // bitonic sort exact keys ascending
    for (int k = 2; k <= P; k <<= 1)
        for (int j = k >> 1; j > 0; j >>= 1) {
            for (int i = tid; i < P; i += 256) {
                int ixj = i ^ j;
                if (ixj > i) {
                    unsigned long long a = buf[i], c = buf[ixj];
                    if ((a > c) == ((i & k) == 0)) { buf[i] = c; buf[ixj] = a; }
                }
            }
            __syncthreads();
        }

    // local layer + prefix softmax on ranks 0..31
    if (tid < KSEL) {
        unsigned long long key = buf[tid];
        float d2v = dec((unsigned)(key >> 32));
        int   idx = (int)(key & 0xffffffffu);
        float sc  = Y[idx];
        float nd  = (sys[idx] == qsys[b]) ? fmaf(d2v, W[1], bias[1]) : fmaf(d2v, W[0], bias[0]);
        float neg = -nd;
        float mmax = neg;
        #pragma unroll
        for (int off = 16; off > 0; off >>= 1)
            mmax = fmaxf(mmax, __shfl_xor_sync(0xffffffffu, mmax, off));
        float w  = expf(neg - mmax);
        float ws = w * sc;
        float cw = w, cws = ws;
        #pragma unroll
        for (int off = 1; off < KSEL; off <<= 1) {
            float tw  = __shfl_up_sync(0xffffffffu, cw,  off);
            float tws = __shfl_up_sync(0xffffffffu, cws, off);
            if (tid >= off) { cw += tw; cws += tws; }
        }
        out[(size_t)b * KSEL + tid] = nd;
        out[(size_t)B * KSEL + (size_t)b * KSEL + tid] = cws / cw;
    }
}

extern "C" void kernel_launch(void* const* d_in, const int* in_sizes, int n_in,
                              void* d_out, int out_size)
{
    const float* Q    = (const float*)d_in[0];
    const int*   qsys = (const int*)  d_in[1];
    const float* X    = (const float*)d_in[2];
    const float* Y    = (const float*)d_in[3];
    const int*   sys  = (const int*)  d_in[4];
    const float* W    = (const float*)d_in[5];
    const float* bias = (const float*)d_in[6];
    float* out = (float*)d_out;

    int B = in_sizes[1];
    int N = in_sizes[3];
    int ntiles = (N + TILE_N - 1) / TILE_N;

    const int smem = STAGES * STAGE_BYTES;   // 114688 (also covers 256*SPITCH*2 staging)
    cudaFuncSetAttribute(gemm_fp8_kernel, cudaFuncAttributeMaxDynamicSharedMemorySize, smem);

    convq_kernel<<<(MAXB * DEMB / 4 + 255) / 256, 256>>>(Q, B * DEMB);
    gemm_fp8_kernel<<<ntiles, 512, smem>>>(X, B, N, ntiles);
    select_kernel<<<B, 256>>>(Q, qsys, X, Y, sys, W, bias, out, B, N, ntiles);
}

// round 8
// speedup vs baseline: 1.0250x; 1.0250x over previous
#include <cuda_runtime.h>
#include <cuda_fp16.h>
#include <math_constants.h>
#include <cstdint>
#include <cstddef>

#define DEMB 768
#define KSEL 32
#define K2   128               // blockmin threshold rank
#define TILE_N 128
#define KC   32                // k elements per chunk
#define NCH  (DEMB / KC)       // 24
#define STAGES 4
#define MAXB 256
#define MAXN 200000
#define MAXT ((MAXN + TILE_N - 1) / TILE_N)   // 1563
#define CCAP 1024
#define BMPAD 2048

// stage layout: A fp8 256 rows x 48B pitch (32B data), B fp8 128 rows x 48B pitch
#define A_PITCH 48
#define B_PITCH 48
#define A_BYTES (256 * A_PITCH)            // 12288
#define B_BYTES (128 * B_PITCH)            // 6144
#define STAGE_BYTES (A_BYTES + B_BYTES)    // 18432

// ---- device scratch ----
__device__ __align__(16) uint8_t g_Q8[MAXB * DEMB];
__device__ __align__(16) uint8_t g_X8[(size_t)MAXN * DEMB];
__device__ __align__(16) float   g_x2g[MAXN];
__device__ __align__(16) float   g_S[(size_t)MAXB * (size_t)MAXN];
__device__ __align__(16) float   g_blkmin[MAXB * MAXT];

__device__ __forceinline__ uint32_t smem_u32(const void* p) {
    uint32_t a;
    asm("{ .reg .u64 t; cvta.to.shared.u64 t, %1; cvt.u32.u64 %0, t; }" : "=r"(a) : "l"(p));
    return a;
}
__device__ __forceinline__ void cp16(uint32_t dst, const void* src) {
    asm volatile("cp.async.ca.shared.global [%0], [%1], 16;" :: "r"(dst), "l"(src));
}
#define CP_COMMIT() asm volatile("cp.async.commit_group;" ::: "memory")
#define CP_WAIT2()  asm volatile("cp.async.wait_group 2;" ::: "memory")

__device__ __forceinline__ uint32_t pack_e4m3(float f0, float f1, float f2, float f3) {
    uint16_t lo, hi;
    asm("cvt.rn.satfinite.e4m3x2.f32 %0, %1, %2;" : "=h"(lo) : "f"(f1), "f"(f0));
    asm("cvt.rn.satfinite.e4m3x2.f32 %0, %1, %2;" : "=h"(hi) : "f"(f3), "f"(f2));
    return (uint32_t)lo | ((uint32_t)hi << 16);
}
__device__ __forceinline__ void mma_fp8(float* c, const uint32_t* a, const uint32_t* b) {
    asm volatile(
        "mma.sync.aligned.m16n8k32.row.col.f32.e4m3.e4m3.f32 "
        "{%0,%1,%2,%3}, {%4,%5,%6,%7}, {%8,%9}, {%0,%1,%2,%3};"
        : "+f"(c[0]), "+f"(c[1]), "+f"(c[2]), "+f"(c[3])
        : "r"(a[0]), "r"(a[1]), "r"(a[2]), "r"(a[3]), "r"(b[0]), "r"(b[1]));
}
__device__ __forceinline__ unsigned enc(float f) {
    unsigned u = __float_as_uint(f);
    return (u & 0x80000000u) ? ~u : (u | 0x80000000u);
}
__device__ __forceinline__ float dec(unsigned u) {
    u = (u & 0x80000000u) ? (u & 0x7fffffffu) : ~u;
    return __uint_as_float(u);
}
__device__ __forceinline__ unsigned long long mkkey(float v, int idx) {
    return ((unsigned long long)enc(v) << 32) | (unsigned)idx;
}

// ---------------- Q fp32 -> e4m3 (zero-pad to MAXB rows) ----------------
__global__ void convq_kernel(const float* __restrict__ Q, int total) {
    int i = blockIdx.x * blockDim.x + threadIdx.x;
    if (i < MAXB * DEMB / 4) {
        int e = i * 4;
        float4 v = make_float4(0.f, 0.f, 0.f, 0.f);
        if (e < total) v = *(const float4*)&Q[e];
        ((uint32_t*)g_Q8)[i] = pack_e4m3(v.x, v.y, v.z, v.w);
    }
}

// ---------------- X fp32 -> e4m3 + exact row norms (one read of X) ----------------
__global__ void convx_kernel(const float* __restrict__ X, int N) {
    int w = (int)((blockIdx.x * blockDim.x + threadIdx.x) >> 5);
    int lane = threadIdx.x & 31;
    if (w >= N) return;
    const float4* src = (const float4*)(X + (size_t)w * DEMB);
    uint32_t* dst = (uint32_t*)(g_X8 + (size_t)w * DEMB);
    float s = 0.f;
    #pragma unroll
    for (int i = lane; i < DEMB / 4; i += 32) {
        float4 v = src[i];
        dst[i] = pack_e4m3(v.x, v.y, v.z, v.w);
        s = fmaf(v.x, v.x, fmaf(v.y, v.y, fmaf(v.z, v.z, fmaf(v.w, v.w, s))));
    }
    #pragma unroll
    for (int off = 16; off > 0; off >>= 1) s += __shfl_xor_sync(0xffffffffu, s, off);
    if (lane == 0) g_x2g[w] = s;
}

// ---------------- FP8 MMA GEMM, M=256 x N-tile=128, pure fp8 hot loop ----------------
__global__ __launch_bounds__(512, 1)
void gemm_fp8_kernel(int B, int N, int ntiles)
{
    extern __shared__ __align__(16) char dsm[];
    __shared__ float    x2p[TILE_N];
    __shared__ unsigned bmu[256];

    const int tid  = threadIdx.x;
    const int lane = tid & 31;
    const int warp = tid >> 5;
    const int wm = warp >> 2, wn = warp & 3;
    const int fr = lane >> 2, fc = lane & 3;
    const int n0 = blockIdx.x * TILE_N;

    const uint32_t sb = smem_u32(dsm);

    // A cp.async: 256 rows x 2 x 16B chunks, one per thread
    const int rA = tid >> 1, hA = tid & 1;
    const char* asrc = (const char*)g_Q8 + (size_t)rA * DEMB + hA * 16;
    const uint32_t adst = sb + rA * A_PITCH + hA * 16;

    // B cp.async: 128 rows x 2 x 16B chunks, threads 0..255
    const int rB = (tid & 255) >> 1, hB = tid & 1;
    const char* bsrc = (const char*)g_X8 + (size_t)min(n0 + rB, N - 1) * DEMB + hB * 16;
    const uint32_t bdst = sb + A_BYTES + rB * B_PITCH + hB * 16;
    const bool doB = tid < 256;

    if (tid < 256) bmu[tid] = 0xFFFFFFFFu;
    if (tid < TILE_N) x2p[tid] = g_x2g[min(n0 + tid, N - 1)];

    // prologue: stages 0..2
    #pragma unroll
    for (int s = 0; s < 3; s++) {
        cp16(adst + s * STAGE_BYTES, asrc + s * KC);
        if (doB) cp16(bdst + s * STAGE_BYTES, bsrc + s * KC);
        CP_COMMIT();
    }

    float acc[4][4][4];
    #pragma unroll
    for (int mi = 0; mi < 4; mi++)
        #pragma unroll
        for (int ni = 0; ni < 4; ni++)
            #pragma unroll
            for (int r = 0; r < 4; r++) acc[mi][ni][r] = 0.f;

    for (int ch = 0; ch < NCH; ch++) {
        const int st = ch & 3;
        CP_WAIT2();
        __syncthreads();

        if (ch + 3 < NCH) {
            const int so = ((ch + 3) & 3) * STAGE_BYTES;
            const int ko = (ch + 3) * KC;
            cp16(adst + so, asrc + ko);
            if (doB) cp16(bdst + so, bsrc + ko);
        }
        CP_COMMIT();

        const char* Ab = dsm + st * STAGE_BYTES;
        const char* Bb = Ab + A_BYTES;

        // B fragments: direct fp8 LDS (conflict-free, pitch 48)
        uint32_t bf[4][2];
        #pragma unroll
        for (int ni = 0; ni < 4; ni++) {
            const int n = wn * 32 + ni * 8 + fr;
            bf[ni][0] = *(const uint32_t*)(Bb + n * B_PITCH + fc * 4);
            bf[ni][1] = *(const uint32_t*)(Bb + n * B_PITCH + 16 + fc * 4);
        }

        // A fragments + MMAs
        #pragma unroll
        for (int mi = 0; mi < 4; mi++) {
            const int row = wm * 64 + mi * 16 + fr;
            uint32_t a[4];
            a[0] = *(const uint32_t*)(Ab + row * A_PITCH + fc * 4);
            a[1] = *(const uint32_t*)(Ab + (row + 8) * A_PITCH + fc * 4);
            a[2] = *(const uint32_t*)(Ab + row * A_PITCH + 16 + fc * 4);
            a[3] = *(const uint32_t*)(Ab + (row + 8) * A_PITCH + 16 + fc * 4);
            #pragma unroll
            for (int ni = 0; ni < 4; ni++)
                mma_fp8(acc[mi][ni], a, bf[ni]);
        }
        __syncthreads();
    }

    // ---- epilogue: dist = x2 - 2*dot, direct float2 stores + blockmin ----
    #pragma unroll
    for (int mi = 0; mi < 4; mi++) {
        const int R = wm * 64 + mi * 16 + fr;
        float mn0 = CUDART_INF_F, mn1 = CUDART_INF_F;
        #pragma unroll
        for (int ni = 0; ni < 4; ni++) {
            const int c = wn * 32 + ni * 8 + 2 * fc;
            const int n = n0 + c;
            const bool ok0 = n < N, ok1 = (n + 1) < N;
            float x2c = x2p[c], x2d = x2p[c + 1];
            float v0 = fmaf(-2.f, acc[mi][ni][0], x2c);
            float v1 = fmaf(-2.f, acc[mi][ni][1], x2d);
            float v2 = fmaf(-2.f, acc[mi][ni][2], x2c);
            float v3 = fmaf(-2.f, acc[mi][ni][3], x2d);
            if (R < B) {
                if (ok0 && ok1) *(float2*)&g_S[(size_t)R * N + n] = make_float2(v0, v1);
                else if (ok0) g_S[(size_t)R * N + n] = v0;
            }
            if (R + 8 < B) {
                if (ok0 && ok1) *(float2*)&g_S[(size_t)(R + 8) * N + n] = make_float2(v2, v3);
                else if (ok0) g_S[(size_t)(R + 8) * N + n] = v2;
            }
            if (ok0) { mn0 = fminf(mn0, v0); mn1 = fminf(mn1, v2); }
            if (ok1) { mn0 = fminf(mn0, v1); mn1 = fminf(mn1, v3); }
        }
        #pragma unroll
        for (int off = 1; off < 4; off <<= 1) {
            mn0 = fminf(mn0, __shfl_xor_sync(0xffffffffu, mn0, off));
            mn1 = fminf(mn1, __shfl_xor_sync(0xffffffffu, mn1, off));
        }
        if (fc == 0) {
            atomicMin(&bmu[R], enc(mn0));
            atomicMin(&bmu[R + 8], enc(mn1));
        }
    }
    __syncthreads();
    if (tid < 256)
        g_blkmin[tid * ntiles + blockIdx.x] = dec(bmu[tid]);
}

// ---------------- select: blockmin t0 -> gather -> refine ALL -> sort exact ----------------
__global__ __launch_bounds__(256)
void select_kernel(const float* __restrict__ Q, const int* __restrict__ qsys,
                   const float* __restrict__ X, const float* __restrict__ Y,
                   const int* __restrict__ sys, const float* __restrict__ W,
                   const float* __restrict__ bias, float* __restrict__ out,
                   int B, int N, int ntiles)
{
    __shared__ float qs[DEMB];
    __shared__ float red[256];
    __shared__ unsigned long long buf[CCAP];   // 8KB: blockmin arena, then refined keys
    __shared__ int   cand[CCAP];
    __shared__ int   blist[CCAP];
    __shared__ int   sh_cnt, sh_nblk;

    const int b = blockIdx.x, tid = threadIdx.x;
    const int warp = tid >> 5, lane = tid & 31;

    float q2p = 0.f;
    for (int k = tid; k < DEMB; k += 256) {
        float v = Q[(size_t)b * DEMB + k];
        qs[k] = v; q2p = fmaf(v, v, q2p);
    }
    red[tid] = q2p; __syncthreads();
    for (int s = 128; s > 0; s >>= 1) { if (tid < s) red[tid] += red[tid + s]; __syncthreads(); }
    const float q2 = red[0];

    float* bms = (float*)buf;
    const float* bmrow = &g_blkmin[b * ntiles];
    for (int i = tid; i < BMPAD; i += 256)
        bms[i] = (i < ntiles) ? bmrow[i] : CUDART_INF_F;
    if (tid == 0) { sh_cnt = 0; sh_nblk = 0; }
    __syncthreads();

    for (int k = 2; k <= BMPAD; k <<= 1)
        for (int j = k >> 1; j > 0; j >>= 1) {
            for (int i = tid; i < BMPAD; i += 256) {
                int ixj = i ^ j;
                if (ixj > i) {
                    float a = bms[i], c = bms[ixj];
                    if ((a > c) == ((i & k) == 0)) { bms[i] = c; bms[ixj] = a; }
                }
            }
            __syncthreads();
        }
    const float t0 = bms[K2 - 1];
    __syncthreads();

    for (int i = tid; i < ntiles; i += 256)
        if (bmrow[i] <= t0) {
            int p = atomicAdd(&sh_nblk, 1);
            if (p < CCAP) blist[p] = i;
        }
    __syncthreads();
    int nblk = sh_nblk; if (nblk > CCAP) nblk = CCAP;

    const float* srow = &g_S[(size_t)b * N];
    for (int e = tid; e < nblk * TILE_N; e += 256) {
        int blk = blist[e >> 7];
        int n = blk * TILE_N + (e & (TILE_N - 1));
        if (n < N) {
            float v = srow[n];
            if (v <= t0) {
                int p = atomicAdd(&sh_cnt, 1);
                if (p < CCAP) cand[p] = n;
            }
        }
    }
    __syncthreads();
    int cnt = sh_cnt; if (cnt > CCAP) cnt = CCAP;

    int P = 64; while (P < cnt) P <<= 1;
    for (int i = tid; i < P; i += 256) buf[i] = ~0ULL;
    __syncthreads();

    // exact fp32 refine of ALL candidates
    for (int c = warp; c < cnt; c += 8) {
        const int idx = cand[c];
        const float* xr = &X[(size_t)idx * DEMB];
        float dot = 0.f, xx = 0.f;
        for (int k = lane; k < DEMB; k += 32) {
            float xv = xr[k];
            dot = fmaf(qs[k], xv, dot);
            xx  = fmaf(xv, xv, xx);
        }
        #pragma unroll
        for (int off = 16; off > 0; off >>= 1) {
            dot += __shfl_xor_sync(0xffffffffu, dot, off);
            xx  += __shfl_xor_sync(0xffffffffu, xx,  off);
        }
        if (lane == 0) buf[c] = mkkey(fmaf(-2.f, dot, q2 + xx), idx);
    }
    __syncthreads();

    for (int k = 2; k <= P; k <<= 1)
        for (int j = k >> 1; j > 0; j >>= 1) {
            for (int i = tid; i < P; i += 256) {
                int ixj = i ^ j;
                if (ixj > i) {
                    unsigned long long a = buf[i], c = buf[ixj];
                    if ((a > c) == ((i & k) == 0)) { buf[i] = c; buf[ixj] = a; }
                }
            }
            __syncthreads();
        }

    if (tid < KSEL) {
        unsigned long long key = buf[tid];
        float d2v = dec((unsigned)(key >> 32));
        int   idx = (int)(key & 0xffffffffu);
        float sc  = Y[idx];
        float nd  = (sys[idx] == qsys[b]) ? fmaf(d2v, W[1], bias[1]) : fmaf(d2v, W[0], bias[0]);
        float neg = -nd;
        float mmax = neg;
        #pragma unroll
        for (int off = 16; off > 0; off >>= 1)
            mmax = fmaxf(mmax, __shfl_xor_sync(0xffffffffu, mmax, off));
        float w  = expf(neg - mmax);
        float ws = w * sc;
        float cw = w, cws = ws;
        #pragma unroll
        for (int off = 1; off < KSEL; off <<= 1) {
            float tw  = __shfl_up_sync(0xffffffffu, cw,  off);
            float tws = __shfl_up_sync(0xffffffffu, cws, off);
            if (tid >= off) { cw += tw; cws += tws; }
        }
        out[(size_t)b * KSEL + tid] = nd;
        out[(size_t)B * KSEL + (size_t)b * KSEL + tid] = cws / cw;
    }
}

extern "C" void kernel_launch(void* const* d_in, const int* in_sizes, int n_in,
                              void* d_out, int out_size)
{
    const float* Q    = (const float*)d_in[0];
    const int*   qsys = (const int*)  d_in[1];
    const float* X    = (const float*)d_in[2];
    const float* Y    = (const float*)d_in[3];
    const int*   sys  = (const int*)  d_in[4];
    const float* W    = (const float*)d_in[5];
    const float* bias = (const float*)d_in[6];
    float* out = (float*)d_out;

    int B = in_sizes[1];
    int N = in_sizes[3];
    int ntiles = (N + TILE_N - 1) / TILE_N;

    const int smem = STAGES * STAGE_BYTES;   // 73728
    cudaFuncSetAttribute(gemm_fp8_kernel, cudaFuncAttributeMaxDynamicSharedMemorySize, smem);

    convq_kernel<<<(MAXB * DEMB / 4 + 255) / 256, 256>>>(Q, B * DEMB);
    convx_kernel<<<(N + 7) / 8, 256>>>(X, N);
    gemm_fp8_kernel<<<ntiles, 512, smem>>>(B, N, ntiles);
    select_kernel<<<B, 256>>>(Q, qsys, X, Y, sys, W, bias, out, B, N, ntiles);
}